// round 2
// baseline (speedup 1.0000x reference)
#include <cuda_runtime.h>

// ---------------------------------------------------------------------------
// ContrastiveCRFLoss — B200 (sm_100a), round 2
//
// out[n,a,b] = -( sum_k C[n,k,a]*C[n,k,b] ) *
//              ( E1(a,b)*exp(-gd(n,a,b)/0.3) + E2(a,b) )
// E1 = 10*exp(-cd), E2 = 3*exp(-10*cd)  — batch independent, precomputed
//
// k0: fused gather of sampled columns (clusters + guidance + coords)
// k1: E1/E2 field precompute (1024x1024, L2 resident)
// k2: main 64x64-tile kernel, 256 thr, 4x4 micro-tile, f32x2 FMA with
//     zero-MOV operand loads (ld.shared.v2.u64 + duplicated A fragment),
//     E tiles staged in SMEM once per CTA and reused across 8 batches.
// ---------------------------------------------------------------------------

#define NB    32
#define KC    27
#define CG    3
#define NS    1000
#define NPAD  1024
#define HW    256
#define TILE  64
#define NT    16            // 1024 / 64
#define BSPLIT 4
#define BPER  (NB / BSPLIT)
#define EP    1024          // E-field stride

// ---- device scratch --------------------------------------------------------
__device__ float d_selC[NB * KC * NPAD];
__device__ float d_selG[NB * CG * NPAD];
__device__ float d_ga2 [NB * NPAD];
__device__ float d_rf  [NPAD];
__device__ float d_cf  [NPAD];
__device__ float d_E1  [EP * EP];      // 4 MB
__device__ float d_E2  [EP * EP];      // 4 MB

typedef unsigned long long ull;

__device__ __forceinline__ ull ffma2(ull a, ull b, ull c) {
    ull d;
    asm("fma.rn.f32x2 %0, %1, %2, %3;" : "=l"(d) : "l"(a), "l"(b), "l"(c));
    return d;
}
__device__ __forceinline__ float2 unpack2(ull v) {
    float2 r;
    asm("mov.b64 {%0, %1}, %2;" : "=f"(r.x), "=f"(r.y) : "l"(v));
    return r;
}
__device__ __forceinline__ void lds_v2u64(ull& lo, ull& hi, unsigned addr) {
    asm volatile("ld.shared.v2.u64 {%0, %1}, [%2];"
                 : "=l"(lo), "=l"(hi) : "r"(addr));
}
__device__ __forceinline__ unsigned smem_u32(const void* p) {
    unsigned a;
    asm("{ .reg .u64 t; cvta.to.shared.u64 t, %1; cvt.u32.u64 %0, t; }"
        : "=r"(a) : "l"(p));
    return a;
}

// ---------------------------------------------------------------------------
// k0: fused gather
// ---------------------------------------------------------------------------
__global__ void gather_all_k(const float* __restrict__ guidance,
                             const float* __restrict__ clusters,
                             const int*   __restrict__ coords) {
    int idx = blockIdx.x * blockDim.x + threadIdx.x;
    if (idx >= NB * KC * NS) return;
    int s  = idx % NS;
    int nk = idx / NS;
    int r = coords[s];
    int c = coords[NS + s];
    d_selC[nk * NPAD + s] = clusters[((size_t)nk * HW + r) * HW + c];

    if (idx < NB * NS) {
        int n = nk;   // here nk == n since idx < NB*NS means nk in [0,NB)
        float g0 = guidance[(((size_t)n * CG + 0) * HW + r) * HW + c];
        float g1 = guidance[(((size_t)n * CG + 1) * HW + r) * HW + c];
        float g2 = guidance[(((size_t)n * CG + 2) * HW + r) * HW + c];
        d_selG[(n * CG + 0) * NPAD + s] = g0;
        d_selG[(n * CG + 1) * NPAD + s] = g1;
        d_selG[(n * CG + 2) * NPAD + s] = g2;
        d_ga2[n * NPAD + s] = g0 * g0 + g1 * g1 + g2 * g2;
    }
    if (idx < NS) {
        d_rf[idx] = (float)r;
        d_cf[idx] = (float)c;
    }
}

// ---------------------------------------------------------------------------
// k1: coordinate-kernel field precompute (batch independent)
// ---------------------------------------------------------------------------
__global__ void epre_k() {
    int idx = blockIdx.x * blockDim.x + threadIdx.x;   // 1M threads
    int a = idx >> 10;
    int b = idx & (EP - 1);
    int ac = min(a, NS - 1);
    int bc = min(b, NS - 1);
    float dr = d_rf[ac] - d_rf[bc];
    float dc = d_cf[ac] - d_cf[bc];
    float cd = dr * dr + dc * dc;
    d_E1[idx] = 10.0f * __expf(-cd);
    d_E2[idx] = 3.0f * __expf(-10.0f * cd);
}

// ---------------------------------------------------------------------------
// k2: main kernel
// SMEM layout (floats):
//   sE1[64*64]  sE2[64*64]  sCaD[27*128]  sCb[27*64]
//   sGa[3*64]  sGb[3*64]  sga2[64]  sgb2[64]
// ---------------------------------------------------------------------------
#define OFF_E1   0
#define OFF_E2   (TILE * TILE)                 // 4096
#define OFF_CAD  (2 * TILE * TILE)             // 8192
#define OFF_CB   (OFF_CAD + KC * 2 * TILE)     // 11648
#define OFF_GA   (OFF_CB + KC * TILE)          // 13376
#define OFF_GB   (OFF_GA + CG * TILE)          // 13568
#define OFF_GA2  (OFF_GB + CG * TILE)          // 13760
#define OFF_GB2  (OFF_GA2 + TILE)              // 13824
#define SMEM_FLOATS (OFF_GB2 + TILE)           // 13888
#define SMEM_BYTES  (SMEM_FLOATS * 4)          // 55552

__global__ void __launch_bounds__(256)
crf_main_k(float* __restrict__ out) {
    extern __shared__ float sm[];
    float* sE1  = sm + OFF_E1;
    float* sE2  = sm + OFF_E2;
    float* sCaD = sm + OFF_CAD;
    float* sCb  = sm + OFF_CB;
    float* sGa  = sm + OFF_GA;
    float* sGb  = sm + OFF_GB;
    float* sga2 = sm + OFF_GA2;
    float* sgb2 = sm + OFF_GB2;

    const int tid = threadIdx.x;
    const int tx  = tid & 15;          // b direction
    const int ty  = tid >> 4;          // a direction
    const int Bb  = blockIdx.x * TILE;
    const int Ab  = blockIdx.y * TILE;
    const int a0  = ty * 4;
    const int b0  = tx * 4;

    // ---- stage E tiles once per CTA (float4, coalesced) ----
    {
        const float4* e1g = (const float4*)(d_E1 + (size_t)Ab * EP + Bb);
        const float4* e2g = (const float4*)(d_E2 + (size_t)Ab * EP + Bb);
        float4* e1s = (float4*)sE1;
        float4* e2s = (float4*)sE2;
        for (int t = tid; t < TILE * TILE / 4; t += 256) {
            int i = t >> 4;              // row
            int j = t & 15;              // float4 col
            e1s[t] = e1g[i * (EP / 4) + j];
            e2s[t] = e2g[i * (EP / 4) + j];
        }
    }

    const unsigned smBase = smem_u32(sm);
    const bool bvalid = (Bb + b0) < NS;          // NS % 4 == 0
    const float inv2beta = -3.33333333f;

    for (int nb = 0; nb < BPER; nb++) {
        const int n = blockIdx.z * BPER + nb;

        __syncthreads();      // covers E staging (first iter) + prior reads

        // ---- stage C tiles (A duplicated for f32x2 broadcast) ----
        const float* Cbase = d_selC + (size_t)n * KC * NPAD;
        for (int t = tid; t < KC * TILE; t += 256) {
            int k = t >> 6, i = t & 63;
            float va = Cbase[k * NPAD + min(Ab + i, NS - 1)];
            float2 vd = make_float2(va, va);
            *(float2*)&sCaD[k * 128 + 2 * i] = vd;
            sCb[k * 64 + i] = Cbase[k * NPAD + min(Bb + i, NS - 1)];
        }
        if (tid < CG * TILE) {
            const float* Gbase = d_selG + (size_t)n * CG * NPAD;
            int ch = tid >> 6, i = tid & 63;
            sGa[ch * 64 + i] = Gbase[ch * NPAD + min(Ab + i, NS - 1)];
            sGb[ch * 64 + i] = Gbase[ch * NPAD + min(Bb + i, NS - 1)];
        }
        if (tid < TILE) {
            sga2[tid] = d_ga2[n * NPAD + min(Ab + tid, NS - 1)];
            sgb2[tid] = d_ga2[n * NPAD + min(Bb + tid, NS - 1)];
        }
        __syncthreads();

        // ---- 27-term gram dot: per k = 3 LDS.128 + 8 FFMA2, zero MOVs ----
        ull acc00 = 0, acc01 = 0, acc10 = 0, acc11 = 0;
        ull acc20 = 0, acc21 = 0, acc30 = 0, acc31 = 0;

        unsigned aAddr = smBase + (OFF_CAD + 2 * a0) * 4;
        unsigned bAddr = smBase + (OFF_CB + b0) * 4;

        #pragma unroll
        for (int k = 0; k < KC; k++) {
            ull ad0, ad1, ad2, ad3, bp01, bp23;
            lds_v2u64(ad0, ad1, aAddr);          // (a0,a0),(a1,a1)
            lds_v2u64(ad2, ad3, aAddr + 16);     // (a2,a2),(a3,a3)
            lds_v2u64(bp01, bp23, bAddr);        // (b0,b1),(b2,b3)
            acc00 = ffma2(ad0, bp01, acc00);
            acc01 = ffma2(ad0, bp23, acc01);
            acc10 = ffma2(ad1, bp01, acc10);
            acc11 = ffma2(ad1, bp23, acc11);
            acc20 = ffma2(ad2, bp01, acc20);
            acc21 = ffma2(ad2, bp23, acc21);
            acc30 = ffma2(ad3, bp01, acc30);
            acc31 = ffma2(ad3, bp23, acc31);
            aAddr += 128 * 4;
            bAddr += 64 * 4;
        }

        // ---- epilogue ----
        float gaCh[CG][4], gbCh[CG][4];
        #pragma unroll
        for (int ch = 0; ch < CG; ch++) {
            float4 t = *(const float4*)&sGa[ch * 64 + a0];
            gaCh[ch][0] = t.x; gaCh[ch][1] = t.y; gaCh[ch][2] = t.z; gaCh[ch][3] = t.w;
            float4 u = *(const float4*)&sGb[ch * 64 + b0];
            gbCh[ch][0] = u.x; gbCh[ch][1] = u.y; gbCh[ch][2] = u.z; gbCh[ch][3] = u.w;
        }
        float4 ga2q = *(const float4*)&sga2[a0];
        float4 gb2q = *(const float4*)&sgb2[b0];
        float ga2a[4] = {ga2q.x, ga2q.y, ga2q.z, ga2q.w};
        float gb2a[4] = {gb2q.x, gb2q.y, gb2q.z, gb2q.w};

        ull accs[4][2] = {{acc00, acc01}, {acc10, acc11},
                          {acc20, acc21}, {acc30, acc31}};

        size_t outBase = ((size_t)n * NS + (Ab + a0)) * NS + (Bb + b0);

        #pragma unroll
        for (int i = 0; i < 4; i++) {
            float2 d01 = unpack2(accs[i][0]);
            float2 d23 = unpack2(accs[i][1]);
            float dots[4] = {d01.x, d01.y, d23.x, d23.y};
            float4 e1 = *(const float4*)&sE1[(a0 + i) * TILE + b0];
            float4 e2 = *(const float4*)&sE2[(a0 + i) * TILE + b0];
            float e1a[4] = {e1.x, e1.y, e1.z, e1.w};
            float e2a[4] = {e2.x, e2.y, e2.z, e2.w};
            float4 res;
            float* rp = (float*)&res;
            #pragma unroll
            for (int j = 0; j < 4; j++) {
                float dot3 = gaCh[0][i] * gbCh[0][j];
                dot3 = fmaf(gaCh[1][i], gbCh[1][j], dot3);
                dot3 = fmaf(gaCh[2][i], gbCh[2][j], dot3);
                float gd = ga2a[i] + gb2a[j] - 2.0f * dot3;
                float eg = __expf(gd * inv2beta);
                float s  = fmaf(e1a[j], eg, e2a[j]);
                rp[j] = -dots[j] * s;
            }
            int arow = Ab + a0 + i;
            if (bvalid && arow < NS) {
                *(float4*)(out + outBase + (size_t)i * NS) = res;
            }
        }
    }
}

// ---------------------------------------------------------------------------
extern "C" void kernel_launch(void* const* d_in, const int* in_sizes, int n_in,
                              void* d_out, int out_size) {
    const float* guidance = (const float*)d_in[0];
    const float* clusters = (const float*)d_in[1];
    const int*   coords   = (const int*)d_in[2];
    float* out = (float*)d_out;

    cudaFuncSetAttribute(crf_main_k,
                         cudaFuncAttributeMaxDynamicSharedMemorySize,
                         SMEM_BYTES);

    gather_all_k<<<(NB * KC * NS + 255) / 256, 256>>>(guidance, clusters, coords);
    epre_k<<<(EP * EP) / 256, 256>>>();

    dim3 grid(NT, NT, BSPLIT);
    crf_main_k<<<grid, 256, SMEM_BYTES>>>(out);
}

// round 3
// speedup vs baseline: 2.2612x; 2.2612x over previous
#include <cuda_runtime.h>

// ---------------------------------------------------------------------------
// ContrastiveCRFLoss — B200 (sm_100a), round 3: exploit exact-zero sparsity.
//
// sim_kernel(a,b) = 10*exp(-cd - gd/0.3) + 3*exp(-10*cd),  cd = pixel dist^2.
// For integer cd >= 106 both exp terms round to exactly 0.0f (beyond denormal
// range), so out[n,a,b] == -0.0 exactly. Only pairs with cd <= 105 (~6k of 1M,
// batch-independent) need computing.
//
// k0 gather_k : per-(sample,batch) 128B record [C0..C26, G0..G2, rf, cf]
// k1 zfill_k  : zero the 128 MB output (irreducible stream)
// k2 pairs_k  : enumerate active pairs (cd <= 105) via atomic append
// k3 sparse_k : warp per pair, lane = batch; exact formula, scatter stores
// ---------------------------------------------------------------------------

#define NB    32
#define KC    27
#define NS    1000
#define HW    256
#define REC   32                    // floats per (sample, batch) record
#define MAXP  32768                 // pair-list capacity (>5x worst case)
#define CD_MAX 105.0f

__device__ float    d_rec[NS * NB * REC];   // 4 MB, L2-resident
__device__ unsigned d_pairs[MAXP];
__device__ int      d_npairs;

// ---------------------------------------------------------------------------
// k0: gather records.  idx enumerates (s, n, k) with k fastest -> writes are
// near-contiguous per (s,n) 128B record.
// ---------------------------------------------------------------------------
__global__ void gather_k(const float* __restrict__ guidance,
                         const float* __restrict__ clusters,
                         const int*   __restrict__ coords) {
    int idx = blockIdx.x * blockDim.x + threadIdx.x;
    if (idx == 0) d_npairs = 0;
    if (idx >= NS * NB * KC) return;

    int s   = idx / (NB * KC);
    int rem = idx % (NB * KC);
    int n   = rem / KC;
    int k   = rem % KC;

    int r = __ldg(&coords[s]);
    int c = __ldg(&coords[NS + s]);

    float* rec = d_rec + ((size_t)s * NB + n) * REC;

    rec[k] = __ldg(&clusters[(((size_t)n * KC + k) * HW + r) * HW + c]);

    if (k < 3) {
        rec[27 + k] = __ldg(&guidance[(((size_t)n * 3 + k) * HW + r) * HW + c]);
    }
    if (k == 0) {
        rec[30] = (float)r;
        rec[31] = (float)c;
    }
}

// ---------------------------------------------------------------------------
// k1: zero-fill output (float4 grid-stride)
// ---------------------------------------------------------------------------
__global__ void zfill_k(float4* __restrict__ out, int n4) {
    int stride = gridDim.x * blockDim.x;
    float4 z = make_float4(0.f, 0.f, 0.f, 0.f);
    for (int i = blockIdx.x * blockDim.x + threadIdx.x; i < n4; i += stride)
        out[i] = z;
}

// ---------------------------------------------------------------------------
// k2: active-pair enumeration over the 1000x1000 ordered-pair grid
// ---------------------------------------------------------------------------
__global__ void pairs_k(const int* __restrict__ coords) {
    int idx = blockIdx.x * blockDim.x + threadIdx.x;   // 1024*1024 threads
    int a = idx >> 10;
    int b = idx & 1023;
    if (a >= NS || b >= NS) return;

    float dr = (float)(__ldg(&coords[a])      - __ldg(&coords[b]));
    float dc = (float)(__ldg(&coords[NS + a]) - __ldg(&coords[NS + b]));
    float cd = dr * dr + dc * dc;
    if (cd <= CD_MAX) {
        int pos = atomicAdd(&d_npairs, 1);
        if (pos < MAXP) d_pairs[pos] = ((unsigned)a << 16) | (unsigned)b;
    }
}

// ---------------------------------------------------------------------------
// k3: sparse compute.  One warp per active pair; lane = batch index.
// Each lane reads two 128B records (8 x LDG.128 each), computes the exact
// reference formula, scatters one float.
// ---------------------------------------------------------------------------
__global__ void __launch_bounds__(256)
sparse_k(float* __restrict__ out) {
    int gw   = (blockIdx.x * blockDim.x + threadIdx.x) >> 5;  // pair index
    int lane = threadIdx.x & 31;                               // batch index

    int np = d_npairs;
    if (np > MAXP) np = MAXP;
    if (gw >= np) return;

    unsigned pr = d_pairs[gw];
    int a = (int)(pr >> 16);
    int b = (int)(pr & 0xFFFFu);

    const float4* ra4 = (const float4*)(d_rec + ((size_t)a * NB + lane) * REC);
    const float4* rb4 = (const float4*)(d_rec + ((size_t)b * NB + lane) * REC);

    float4 A[8], B[8];
    #pragma unroll
    for (int i = 0; i < 8; i++) { A[i] = ra4[i]; B[i] = rb4[i]; }

    const float* ra = (const float*)A;
    const float* rb = (const float*)B;

    float dot = 0.f;
    #pragma unroll
    for (int k = 0; k < KC; k++) dot = fmaf(ra[k], rb[k], dot);

    float gd = 0.f;
    #pragma unroll
    for (int ch = 0; ch < 3; ch++) {
        float d = ra[27 + ch] - rb[27 + ch];
        gd = fmaf(d, d, gd);
    }

    float dr = ra[30] - rb[30];
    float dc = ra[31] - rb[31];
    float cd = dr * dr + dc * dc;

    float s1 = 10.0f * __expf(-cd - gd * 3.33333333f);   // W1*exp(-cd/(2a) - gd/(2b))
    float s2 = 3.0f  * __expf(-10.0f * cd);              // W2*exp(-cd/(2g))

    out[((size_t)lane * NS + a) * NS + b] = -dot * (s1 + s2);
}

// ---------------------------------------------------------------------------
extern "C" void kernel_launch(void* const* d_in, const int* in_sizes, int n_in,
                              void* d_out, int out_size) {
    const float* guidance = (const float*)d_in[0];
    const float* clusters = (const float*)d_in[1];
    const int*   coords   = (const int*)d_in[2];
    float* out = (float*)d_out;

    gather_k<<<(NS * NB * KC + 255) / 256, 256>>>(guidance, clusters, coords);
    zfill_k<<<8192, 256>>>((float4*)out, out_size / 4);
    pairs_k<<<(1024 * 1024) / 256, 256>>>(coords);
    sparse_k<<<MAXP / 8, 256>>>(out);
}

// round 4
// speedup vs baseline: 2.7290x; 1.2069x over previous
#include <cuda_runtime.h>

// ---------------------------------------------------------------------------
// ContrastiveCRFLoss — B200 (sm_100a), round 4.
//
// Exact-zero sparsity: out[n,a,b] != -0.0 only for pairs with integer
// pixel-dist^2 cd <= 105 (~6k of 1M, batch independent).
//
// k0 sort_k   : one-block bitonic sort of samples by r*256+c (gather locality)
// k1 fused_k  : block-role split —
//                 [0,GB)       gather records (sorted order, DRAM-row local)
//                 [GB,GB+ZB)   zero-fill 128MB output
//                 [GB+ZB,...)  active-pair enumeration (stores packed pair + cd)
// k2 sparse_k : warp per pair, lane = batch; records in [s][word][n] layout
//               so every load is a coalesced 128B wavefront.
// ---------------------------------------------------------------------------

#define NB    32
#define KC    27
#define NS    1000
#define HW    256
#define MAXP  32768
#define CD_MAX 105.0f

#define GB 3375                    // gather blocks: 864000 threads
#define ZB 4096                    // zfill blocks:  1M threads x 8 float4
#define PB 4096                    // pairs blocks:  1M threads
#define NBLK (GB + ZB + PB)

// record table, transposed: d_recT[s][word][n], word 0..26=C, 27..29=G
__device__ float    d_recT[NS * 32 * NB];     // 4 MB
__device__ int      d_order[1024];            // spatially sorted sample ids
__device__ unsigned d_pairs[MAXP];            // (a<<10)|b
__device__ float    d_pcd[MAXP];              // cd per pair
__device__ int      d_npairs;

// ---------------------------------------------------------------------------
// k0: bitonic sort of (key = r*256+c, val = s), one block of 1024 threads
// ---------------------------------------------------------------------------
__global__ void __launch_bounds__(1024)
sort_k(const int* __restrict__ coords) {
    __shared__ unsigned sk[1024];
    int tid = threadIdx.x;
    if (tid == 0) d_npairs = 0;

    unsigned key;
    if (tid < NS) {
        unsigned r = (unsigned)coords[tid];
        unsigned c = (unsigned)coords[NS + tid];
        key = ((r * 256u + c) << 10) | (unsigned)tid;
    } else {
        key = 0xFFFFFFFFu;
    }
    sk[tid] = key;
    __syncthreads();

    for (int k = 2; k <= 1024; k <<= 1) {
        for (int j = k >> 1; j > 0; j >>= 1) {
            int ixj = tid ^ j;
            if (ixj > tid) {
                unsigned x = sk[tid], y = sk[ixj];
                bool up = ((tid & k) == 0);
                if ((x > y) == up) { sk[tid] = y; sk[ixj] = x; }
            }
            __syncthreads();
        }
    }
    d_order[tid] = (int)(sk[tid] & 1023u);
}

// ---------------------------------------------------------------------------
// k1: fused gather + zfill + pairs
// ---------------------------------------------------------------------------
__global__ void __launch_bounds__(256)
fused_k(const float* __restrict__ guidance,
        const float* __restrict__ clusters,
        const int*   __restrict__ coords,
        float4* __restrict__ out, int n4) {
    int bid = blockIdx.x;
    int tid = threadIdx.x;

    if (bid < GB) {
        // ---- gather: idx = (n*KC + k)*NS + sIdx, sIdx fastest (sorted) ----
        int idx = bid * 256 + tid;                 // < 864000 exactly
        int nk   = idx / NS;                       // n*27 + k
        int sIdx = idx - nk * NS;
        int n = nk / KC;
        int k = nk - n * KC;

        int s = d_order[sIdx];
        int r = __ldg(&coords[s]);
        int c = __ldg(&coords[NS + s]);
        int px = r * HW + c;

        float v = __ldg(&clusters[((size_t)nk * HW * HW) + px]);
        d_recT[((size_t)s * 32 + k) * NB + n] = v;

        if (k < 3) {
            float g = __ldg(&guidance[(((size_t)n * 3 + k) * HW * HW) + px]);
            d_recT[((size_t)s * 32 + 27 + k) * NB + n] = g;
        }
    } else if (bid < GB + ZB) {
        // ---- zero-fill output ----
        int zidx = (bid - GB) * 256 + tid;         // [0, 1048576)
        float4 z = make_float4(0.f, 0.f, 0.f, 0.f);
        #pragma unroll
        for (int it = 0; it < 8; it++) {
            int i = zidx + it * (ZB * 256);
            if (i < n4) out[i] = z;
        }
    } else {
        // ---- pair enumeration ----
        int idx = (bid - GB - ZB) * 256 + tid;     // [0, 1048576)
        int a = idx >> 10;
        int b = idx & 1023;
        if (a < NS && b < NS) {
            float dr = (float)(__ldg(&coords[a])      - __ldg(&coords[b]));
            float dc = (float)(__ldg(&coords[NS + a]) - __ldg(&coords[NS + b]));
            float cd = dr * dr + dc * dc;
            if (cd <= CD_MAX) {
                int pos = atomicAdd(&d_npairs, 1);
                if (pos < MAXP) {
                    d_pairs[pos] = ((unsigned)a << 10) | (unsigned)b;
                    d_pcd[pos]   = cd;
                }
            }
        }
    }
}

// ---------------------------------------------------------------------------
// k2: sparse compute — warp per pair, lane = batch, coalesced record reads
// ---------------------------------------------------------------------------
__global__ void __launch_bounds__(256)
sparse_k(float* __restrict__ out) {
    int gw   = (blockIdx.x * blockDim.x + threadIdx.x) >> 5;
    int lane = threadIdx.x & 31;

    int np = d_npairs;
    if (np > MAXP) np = MAXP;
    if (gw >= np) return;

    unsigned pr = d_pairs[gw];
    int a = (int)(pr >> 10);
    int b = (int)(pr & 1023u);
    float cd = d_pcd[gw];

    const float* ra = d_recT + (size_t)a * 32 * NB + lane;
    const float* rb = d_recT + (size_t)b * 32 * NB + lane;

    float dot = 0.f;
    #pragma unroll
    for (int k = 0; k < KC; k++)
        dot = fmaf(__ldg(ra + k * NB), __ldg(rb + k * NB), dot);

    float gd = 0.f;
    #pragma unroll
    for (int ch = 0; ch < 3; ch++) {
        float d = __ldg(ra + (27 + ch) * NB) - __ldg(rb + (27 + ch) * NB);
        gd = fmaf(d, d, gd);
    }

    float s1 = 10.0f * __expf(-cd - gd * 3.33333333f);
    float s2 = 3.0f  * __expf(-10.0f * cd);

    out[((size_t)lane * NS + a) * NS + b] = -dot * (s1 + s2);
}

// ---------------------------------------------------------------------------
extern "C" void kernel_launch(void* const* d_in, const int* in_sizes, int n_in,
                              void* d_out, int out_size) {
    const float* guidance = (const float*)d_in[0];
    const float* clusters = (const float*)d_in[1];
    const int*   coords   = (const int*)d_in[2];
    float* out = (float*)d_out;

    sort_k<<<1, 1024>>>(coords);
    fused_k<<<NBLK, 256>>>(guidance, clusters, coords, (float4*)out, out_size / 4);
    sparse_k<<<MAXP / 8, 256>>>(out);
}